// round 12
// baseline (speedup 1.0000x reference)
#include <cuda_runtime.h>
#include <cuda_bf16.h>
#include <stdint.h>

// RayCastLayer, R12: R11's full-line threads + register weights, with the
// 19-output accumulator split into two halves (two passes over the line's 19
// loads) to cut live registers 38->20, enabling 4 CTAs/SM (single wave) and
// deeper LDS pipelining.

#define BOARD 19
#define NPOS  361
#define PW    55            // padded tile width (x shifted by +18)
#define TILE  (BOARD * PW)  // 1045 u64 entries per 2-plane group
#define THREADS 224
#define PLANES 4            // 2 groups x 2 planes

typedef unsigned long long u64;

#define FMA2(a, x, y) asm("fma.rn.f32x2 %0, %1, %2, %0;" : "+l"(a) : "l"(x), "l"(y))
#define ADD2(a, x)    asm("add.rn.f32x2 %0, %0, %1;"     : "+l"(a) : "l"(x))

__device__ __forceinline__ u64 dupf(float w) {
    u64 u;
    const uint32_t b = __float_as_uint(w);
    asm("mov.b64 %0, {%1,%1};" : "=l"(u) : "r"(b));
    return u;
}

__global__ __launch_bounds__(THREADS, 4)
void raycast_kernel(const float* __restrict__ x,
                    const float* __restrict__ weight,
                    float* __restrict__ out,
                    int nplanes)
{
    __shared__ u64 tile[2][TILE];          // [group][19][55], 2 planes as f32x2
    __shared__ u64 bufV[2][NPOS];          // per-family partials per group
    __shared__ u64 bufH[2][NPOS];
    __shared__ u64 bufD1[2][NPOS];
    __shared__ u64 bufD2[2][NPOS];
    __shared__ u64 wls[18], wds[18];       // duplicated weight pairs

    const int tid = threadIdx.x;
    const int g0  = blockIdx.x * PLANES;

    // ---- weights (line / diagonal), duplicated pairs ----
    if (tid < 36) {
        const int f = tid / 18, d = tid - f * 18;
        const u64 v = dupf(weight[f * 18 + d]);
        if (f == 0) wls[d] = v; else wds[d] = v;
    }

    // ---- zero lateral pad columns (disjoint from data fill) ----
    for (int i = tid; i < 2 * BOARD * 36; i += THREADS) {
        const int gg = i / (BOARD * 36);
        const int r  = i - gg * (BOARD * 36);
        const int y  = r / 36;
        const int c  = r - y * 36;
        const int col = (c < 18) ? c : (c + BOARD);   // [0,18) and [37,55)
        tile[gg][y * PW + col] = 0ull;
    }

    // ---- data fill: pack 2 planes per group into f32x2 ----
    for (int i = tid; i < 2 * NPOS; i += THREADS) {
        const int gg = i / NPOS;
        const int p  = i - gg * NPOS;
        const int yy = p / BOARD;
        const int xx = p - yy * BOARD;
        const int pl = g0 + gg * 2;
        const float v0 = (pl     < nplanes) ? x[pl * NPOS + p]       : 0.f;
        const float v1 = (pl + 1 < nplanes) ? x[(pl + 1) * NPOS + p] : 0.f;
        u64 v;
        asm("mov.b64 %0, {%1,%2};" : "=l"(v)
            : "r"(__float_as_uint(v0)), "r"(__float_as_uint(v1)));
        tile[gg][yy * PW + xx + 18] = v;
    }
    __syncthreads();

    // ---- per-thread line parameters (uniform code across families) ----
    const int grp = tid / 112;
    const int lt  = tid - grp * 112;

    int base, stride, fam, line;
    if (lt < 19)      { fam = 0; line = lt;      base = line + 18;      stride = PW;     }
    else if (lt < 38) { fam = 1; line = lt - 19; base = line * PW + 18; stride = 1;      }
    else if (lt < 75) { fam = 2; line = lt - 38; base = line;           stride = PW + 1; }
    else              { fam = 3; line = lt - 75; base = line + 18;      stride = PW - 1; }
    // fam2 (D1): cell k at (y=k, x=line-18+k) -> idx = k*PW + (line+k)
    // fam3 (D2): cell k at (y=k, x=line-k)    -> idx = k*PW + (line-k+18)

    // ---- weight pairs into registers (compile-time indexed below) ----
    const u64* wsel = (fam < 2) ? wls : wds;
    u64 wr[18];
    #pragma unroll
    for (int i = 0; i < 18; i++) wr[i] = wsel[i];

    const u64* tp = tile[grp];

    // scatter helper: one output j -> family buffer
    #define SCATTER(JJ, VAL) do {                                              \
        const int _j = (JJ);                                                   \
        if (fam == 0)      bufV[grp][_j * BOARD + line] = (VAL);               \
        else if (fam == 1) bufH[grp][line * BOARD + _j] = (VAL);               \
        else if (fam == 2) {                                                   \
            const int _xx = _j + line - 18;                                    \
            if (_xx >= 0 && _xx < BOARD) bufD1[grp][_j * BOARD + _xx] = (VAL); \
        } else {                                                               \
            const int _xx = line - _j;                                         \
            if (_xx >= 0 && _xx < BOARD) bufD2[grp][_j * BOARD + _xx] = (VAL); \
        }                                                                      \
    } while (0)

    // ---- half 1: outputs j in [0,10) ----
    {
        u64 acc[10];
        #pragma unroll
        for (int j = 0; j < 10; j++) acc[j] = 0ull;
        #pragma unroll
        for (int k = 0; k < BOARD; k++) {
            const u64 v = tp[base + k * stride];
            #pragma unroll
            for (int j = 0; j < 10; j++) {
                if (j == k) continue;
                const int d = (k > j) ? (k - j) : (j - k);
                FMA2(acc[j], v, wr[d - 1]);
            }
        }
        #pragma unroll
        for (int j = 0; j < 10; j++) SCATTER(j, acc[j]);
    }

    // ---- half 2: outputs j in [10,19) ----
    {
        u64 acc[9];
        #pragma unroll
        for (int j = 0; j < 9; j++) acc[j] = 0ull;
        #pragma unroll
        for (int k = 0; k < BOARD; k++) {
            const u64 v = tp[base + k * stride];
            #pragma unroll
            for (int j = 0; j < 9; j++) {
                const int jj = j + 10;
                if (jj == k) continue;
                const int d = (k > jj) ? (k - jj) : (jj - k);
                FMA2(acc[j], v, wr[d - 1]);
            }
        }
        #pragma unroll
        for (int j = 0; j < 9; j++) SCATTER(j + 10, acc[j]);
    }
    #undef SCATTER

    __syncthreads();

    // ---- combine 4 partials, unpack, coalesced store per plane ----
    for (int i = tid; i < 2 * NPOS; i += THREADS) {
        const int gg = i / NPOS;
        const int p  = i - gg * NPOS;
        u64 s = bufV[gg][p];
        ADD2(s, bufH[gg][p]);
        ADD2(s, bufD1[gg][p]);
        ADD2(s, bufD2[gg][p]);
        uint32_t p0, p1;
        asm("mov.b64 {%0,%1}, %2;" : "=r"(p0), "=r"(p1) : "l"(s));
        const int pl = g0 + gg * 2;
        if (pl     < nplanes) out[pl * NPOS + p]       = __uint_as_float(p0);
        if (pl + 1 < nplanes) out[(pl + 1) * NPOS + p] = __uint_as_float(p1);
    }
}

extern "C" void kernel_launch(void* const* d_in, const int* in_sizes, int n_in,
                              void* d_out, int out_size)
{
    const float* x      = (const float*)d_in[0];   // [32,64,19,19]
    const float* weight = (const float*)d_in[1];   // [2,18]
    float* out          = (float*)d_out;

    const int nplanes = in_sizes[0] / NPOS;        // 2048
    const int grid = (nplanes + PLANES - 1) / PLANES;   // 512

    raycast_kernel<<<grid, THREADS>>>(x, weight, out, nplanes);
}

// round 13
// speedup vs baseline: 1.6099x; 1.6099x over previous
#include <cuda_runtime.h>
#include <cuda_bf16.h>
#include <stdint.h>

// RayCastLayer R13: full-line threads; line preloaded into registers; weights
// streamed from shared (volatile LDS.64 broadcast) so no 36-register weight
// array exists; outputs computed in scalar pairs and scattered immediately.
// 4 CTAs/SM (single wave of 512 CTAs).

#define BOARD 19
#define NPOS  361
#define PW    55            // padded tile width (x shifted by +18)
#define TILE  (BOARD * PW)  // 1045 u64 entries per 2-plane group
#define THREADS 224
#define PLANES 4            // 2 groups x 2 planes

typedef unsigned long long u64;

#define FMA2(a, x, y) asm("fma.rn.f32x2 %0, %1, %2, %0;" : "+l"(a) : "l"(x), "l"(y))
#define ADD2(a, x)    asm("add.rn.f32x2 %0, %0, %1;"     : "+l"(a) : "l"(x))

__device__ __forceinline__ u64 dupf(float w) {
    u64 u;
    const uint32_t b = __float_as_uint(w);
    asm("mov.b64 %0, {%1,%1};" : "=l"(u) : "r"(b));
    return u;
}

// volatile: prevents ptxas from hoisting weights into a register array
__device__ __forceinline__ u64 ldsw(uint32_t a) {
    u64 v;
    asm volatile("ld.shared.b64 %0, [%1];" : "=l"(v) : "r"(a));
    return v;
}

__global__ __launch_bounds__(THREADS, 4)
void raycast_kernel(const float* __restrict__ x,
                    const float* __restrict__ weight,
                    float* __restrict__ out,
                    int nplanes)
{
    __shared__ u64 tile[2][TILE];          // [group][19][55], 2 planes as f32x2
    __shared__ u64 bufV[2][NPOS];          // per-family partials per group
    __shared__ u64 bufH[2][NPOS];
    __shared__ u64 bufD1[2][NPOS];
    __shared__ u64 bufD2[2][NPOS];
    __shared__ u64 wls[18], wds[18];       // duplicated weight pairs

    const int tid = threadIdx.x;
    const int g0  = blockIdx.x * PLANES;

    // ---- weights (line / diagonal), duplicated pairs ----
    if (tid < 36) {
        const int f = tid / 18, d = tid - f * 18;
        const u64 v = dupf(weight[f * 18 + d]);
        if (f == 0) wls[d] = v; else wds[d] = v;
    }

    // ---- zero lateral pad columns (disjoint from data fill) ----
    for (int i = tid; i < BOARD * 36; i += THREADS) {
        const int y = i / 36;
        const int c = i - y * 36;
        const int col = (c < 18) ? c : (c + BOARD);   // [0,18) and [37,55)
        tile[0][y * PW + col] = 0ull;
        tile[1][y * PW + col] = 0ull;
    }

    // ---- data fill: position-major, both groups per iteration ----
    const bool full = (g0 + PLANES <= nplanes);
    for (int p = tid; p < NPOS; p += THREADS) {
        const int yy = p / BOARD;
        const int xx = p - yy * BOARD;
        const int f  = yy * PW + xx + 18;
        #pragma unroll
        for (int gg = 0; gg < 2; gg++) {
            const int pl = g0 + gg * 2;
            float v0, v1;
            if (full) {
                v0 = x[pl * NPOS + p];
                v1 = x[(pl + 1) * NPOS + p];
            } else {
                v0 = (pl     < nplanes) ? x[pl * NPOS + p]       : 0.f;
                v1 = (pl + 1 < nplanes) ? x[(pl + 1) * NPOS + p] : 0.f;
            }
            u64 v;
            asm("mov.b64 %0, {%1,%2};" : "=l"(v)
                : "r"(__float_as_uint(v0)), "r"(__float_as_uint(v1)));
            tile[gg][f] = v;
        }
    }
    __syncthreads();

    // ---- per-thread line parameters (R11-verified mapping) ----
    const int grp = tid / 112;
    const int lt  = tid - grp * 112;

    int base, stride, fam, line;
    if (lt < 19)      { fam = 0; line = lt;      base = line + 18;      stride = PW;     }
    else if (lt < 38) { fam = 1; line = lt - 19; base = line * PW + 18; stride = 1;      }
    else if (lt < 75) { fam = 2; line = lt - 38; base = line;           stride = PW + 1; }
    else              { fam = 3; line = lt - 75; base = line + 18;      stride = PW - 1; }
    // fam2 (D1): cell k at (y=k, x=line-18+k) -> idx = k*PW + (line+k)
    // fam3 (D2): cell k at (y=k, x=line-k)    -> idx = k*PW + (line-k+18)

    const uint32_t wb = (uint32_t)__cvta_generic_to_shared(
                            (fam < 2) ? (const void*)wls : (const void*)wds);

    // ---- preload full line into registers (independent, pipelined LDS) ----
    const u64* tp = tile[grp];
    u64 ln[19];
    #pragma unroll
    for (int k = 0; k < BOARD; k++) ln[k] = tp[base + k * stride];

    // scatter helper: one output j -> family buffer
    #define SCATTER(JJ, VAL) do {                                              \
        const int _j = (JJ);                                                   \
        if (fam == 0)      bufV[grp][_j * BOARD + line] = (VAL);               \
        else if (fam == 1) bufH[grp][line * BOARD + _j] = (VAL);               \
        else if (fam == 2) {                                                   \
            const int _xx = _j + line - 18;                                    \
            if (_xx >= 0 && _xx < BOARD) bufD1[grp][_j * BOARD + _xx] = (VAL); \
        } else {                                                               \
            const int _xx = line - _j;                                         \
            if (_xx >= 0 && _xx < BOARD) bufD2[grp][_j * BOARD + _xx] = (VAL); \
        }                                                                      \
    } while (0)

    // ---- outputs in pairs: pure-register FMAs, weights streamed ----
    #pragma unroll
    for (int jp = 0; jp < 10; jp++) {
        const int j0 = 2 * jp;
        const int j1 = j0 + 1;
        u64 a0 = 0ull, a1 = 0ull;
        #pragma unroll
        for (int k = 0; k < BOARD; k++) {
            if (k != j0) {
                const int d = (k > j0) ? (k - j0) : (j0 - k);
                FMA2(a0, ln[k], ldsw(wb + (uint32_t)((d - 1) * 8)));
            }
            if (j1 < BOARD && k != j1) {
                const int d = (k > j1) ? (k - j1) : (j1 - k);
                FMA2(a1, ln[k], ldsw(wb + (uint32_t)((d - 1) * 8)));
            }
        }
        SCATTER(j0, a0);
        if (j1 < BOARD) SCATTER(j1, a1);
    }
    #undef SCATTER

    __syncthreads();

    // ---- combine 4 partials, unpack, coalesced store per plane ----
    for (int p = tid; p < NPOS; p += THREADS) {
        #pragma unroll
        for (int gg = 0; gg < 2; gg++) {
            u64 s = bufV[gg][p];
            ADD2(s, bufH[gg][p]);
            ADD2(s, bufD1[gg][p]);
            ADD2(s, bufD2[gg][p]);
            uint32_t p0, p1;
            asm("mov.b64 {%0,%1}, %2;" : "=r"(p0), "=r"(p1) : "l"(s));
            const int pl = g0 + gg * 2;
            if (full) {
                out[pl * NPOS + p]       = __uint_as_float(p0);
                out[(pl + 1) * NPOS + p] = __uint_as_float(p1);
            } else {
                if (pl     < nplanes) out[pl * NPOS + p]       = __uint_as_float(p0);
                if (pl + 1 < nplanes) out[(pl + 1) * NPOS + p] = __uint_as_float(p1);
            }
        }
    }
}

extern "C" void kernel_launch(void* const* d_in, const int* in_sizes, int n_in,
                              void* d_out, int out_size)
{
    const float* x      = (const float*)d_in[0];   // [32,64,19,19]
    const float* weight = (const float*)d_in[1];   // [2,18]
    float* out          = (float*)d_out;

    const int nplanes = in_sizes[0] / NPOS;        // 2048
    const int grid = (nplanes + PLANES - 1) / PLANES;   // 512

    raycast_kernel<<<grid, THREADS>>>(x, weight, out, nplanes);
}

// round 14
// speedup vs baseline: 1.6979x; 1.0547x over previous
#include <cuda_runtime.h>
#include <cuda_bf16.h>
#include <stdint.h>

// RayCastLayer R14: R11 champion (full-line threads, register weights) with
// path trims: weights loaded straight from global (no smem staging / no extra
// barrier dependency), merged dual-group prologue+epilogue, single-branch
// scatter. 4 planes per CTA, grid 512, 224 threads.

#define BOARD 19
#define NPOS  361
#define PW    55            // padded tile width (x shifted by +18)
#define TILE  (BOARD * PW)  // 1045 u64 entries per 2-plane group
#define THREADS 224
#define PLANES 4            // 2 groups x 2 planes

typedef unsigned long long u64;

#define FMA2(a, x, y) asm("fma.rn.f32x2 %0, %1, %2, %0;" : "+l"(a) : "l"(x), "l"(y))
#define ADD2(a, x)    asm("add.rn.f32x2 %0, %0, %1;"     : "+l"(a) : "l"(x))

__device__ __forceinline__ u64 dupf(float w) {
    u64 u;
    const uint32_t b = __float_as_uint(w);
    asm("mov.b64 %0, {%1,%1};" : "=l"(u) : "r"(b));
    return u;
}

__global__ __launch_bounds__(THREADS, 3)
void raycast_kernel(const float* __restrict__ x,
                    const float* __restrict__ weight,
                    float* __restrict__ out,
                    int nplanes)
{
    __shared__ u64 tile[2][TILE];          // [group][19][55], 2 planes as f32x2
    __shared__ u64 bufV[2][NPOS];          // per-family partials per group
    __shared__ u64 bufH[2][NPOS];
    __shared__ u64 bufD1[2][NPOS];
    __shared__ u64 bufD2[2][NPOS];

    const int tid = threadIdx.x;
    const int g0  = blockIdx.x * PLANES;

    // ---- zero lateral pad columns (disjoint from data fill) ----
    for (int i = tid; i < BOARD * 36; i += THREADS) {
        const int y = i / 36;
        const int c = i - y * 36;
        const int col = (c < 18) ? c : (c + BOARD);   // [0,18) and [37,55)
        tile[0][y * PW + col] = 0ull;
        tile[1][y * PW + col] = 0ull;
    }

    // ---- data fill: position-major, both groups per iteration ----
    const bool full = (g0 + PLANES <= nplanes);
    for (int p = tid; p < NPOS; p += THREADS) {
        const int yy = p / BOARD;
        const int xx = p - yy * BOARD;
        const int f  = yy * PW + xx + 18;
        #pragma unroll
        for (int gg = 0; gg < 2; gg++) {
            const int pl = g0 + gg * 2;
            float v0, v1;
            if (full) {
                v0 = x[pl * NPOS + p];
                v1 = x[(pl + 1) * NPOS + p];
            } else {
                v0 = (pl     < nplanes) ? x[pl * NPOS + p]       : 0.f;
                v1 = (pl + 1 < nplanes) ? x[(pl + 1) * NPOS + p] : 0.f;
            }
            u64 v;
            asm("mov.b64 %0, {%1,%2};" : "=l"(v)
                : "r"(__float_as_uint(v0)), "r"(__float_as_uint(v1)));
            tile[gg][f] = v;
        }
    }

    // ---- per-thread line parameters (R11-verified mapping) ----
    const int grp = tid / 112;
    const int lt  = tid - grp * 112;

    int base, stride, fam, line;
    if (lt < 19)      { fam = 0; line = lt;      base = line + 18;      stride = PW;     }
    else if (lt < 38) { fam = 1; line = lt - 19; base = line * PW + 18; stride = 1;      }
    else if (lt < 75) { fam = 2; line = lt - 38; base = line;           stride = PW + 1; }
    else              { fam = 3; line = lt - 75; base = line + 18;      stride = PW - 1; }
    // fam2 (D1): cell k at (y=k, x=line-18+k) -> idx = k*PW + (line+k)
    // fam3 (D2): cell k at (y=k, x=line-k)    -> idx = k*PW + (line-k+18)

    // ---- weights straight from global (L2 broadcast), duplicated pairs ----
    // Overlaps the tile-fill LDGs; no smem staging, no extra barrier dep.
    const float* wsrc = weight + ((fam < 2) ? 0 : 18);
    u64 wr[18];
    #pragma unroll
    for (int i = 0; i < 18; i++) wr[i] = dupf(__ldg(wsrc + i));

    __syncthreads();

    // ---- preload full line into registers ----
    const u64* tp = tile[grp];
    u64 ln[19];
    #pragma unroll
    for (int k = 0; k < BOARD; k++) ln[k] = tp[base + k * stride];

    // ---- the transform: 342 FFMA2, all operands in registers ----
    u64 acc[19];
    #pragma unroll
    for (int j = 0; j < 19; j++) acc[j] = 0ull;

    #pragma unroll
    for (int k = 0; k < BOARD; k++) {
        const u64 v = ln[k];
        #pragma unroll
        for (int j = 0; j < BOARD; j++) {
            if (j == k) continue;
            const int d = (k > j) ? (k - j) : (j - k);
            FMA2(acc[j], v, wr[d - 1]);
        }
    }

    // ---- scatter line outputs (single family branch) ----
    if (fam == 0) {
        #pragma unroll
        for (int j = 0; j < BOARD; j++) bufV[grp][j * BOARD + line] = acc[j];
    } else if (fam == 1) {
        #pragma unroll
        for (int j = 0; j < BOARD; j++) bufH[grp][line * BOARD + j] = acc[j];
    } else if (fam == 2) {
        const int off = line - 18;            // x = j + off
        #pragma unroll
        for (int j = 0; j < BOARD; j++) {
            const int xx = j + off;
            if (xx >= 0 && xx < BOARD) bufD1[grp][j * BOARD + xx] = acc[j];
        }
    } else {
        #pragma unroll
        for (int j = 0; j < BOARD; j++) {     // x = line - j
            const int xx = line - j;
            if (xx >= 0 && xx < BOARD) bufD2[grp][j * BOARD + xx] = acc[j];
        }
    }

    __syncthreads();

    // ---- combine 4 partials, unpack, coalesced store per plane ----
    for (int p = tid; p < NPOS; p += THREADS) {
        #pragma unroll
        for (int gg = 0; gg < 2; gg++) {
            u64 s = bufV[gg][p];
            ADD2(s, bufH[gg][p]);
            ADD2(s, bufD1[gg][p]);
            ADD2(s, bufD2[gg][p]);
            uint32_t p0, p1;
            asm("mov.b64 {%0,%1}, %2;" : "=r"(p0), "=r"(p1) : "l"(s));
            const int pl = g0 + gg * 2;
            if (full) {
                out[pl * NPOS + p]       = __uint_as_float(p0);
                out[(pl + 1) * NPOS + p] = __uint_as_float(p1);
            } else {
                if (pl     < nplanes) out[pl * NPOS + p]       = __uint_as_float(p0);
                if (pl + 1 < nplanes) out[(pl + 1) * NPOS + p] = __uint_as_float(p1);
            }
        }
    }
}

extern "C" void kernel_launch(void* const* d_in, const int* in_sizes, int n_in,
                              void* d_out, int out_size)
{
    const float* x      = (const float*)d_in[0];   // [32,64,19,19]
    const float* weight = (const float*)d_in[1];   // [2,18]
    float* out          = (float*)d_out;

    const int nplanes = in_sizes[0] / NPOS;        // 2048
    const int grid = (nplanes + PLANES - 1) / PLANES;   // 512

    raycast_kernel<<<grid, THREADS>>>(x, weight, out, nplanes);
}

// round 15
// speedup vs baseline: 1.8470x; 1.0878x over previous
#include <cuda_runtime.h>
#include <cuda_bf16.h>
#include <stdint.h>

// RayCastLayer R15: phase-interleaving round. One 2-plane group per CTA
// (112 threads), grid 1024 -> 6 resident CTAs/SM whose fill/compute/epilogue
// phases overlap. Compute identical to the R14 champion: full-line threads,
// weights from global into registers, 342 FFMA2 per thread on f32x2 pairs.

#define BOARD 19
#define NPOS  361
#define PW    55            // padded tile width (x shifted by +18)
#define TILE  (BOARD * PW)  // 1045 u64 entries
#define THREADS 112
#define PLANES 2

typedef unsigned long long u64;

#define FMA2(a, x, y) asm("fma.rn.f32x2 %0, %1, %2, %0;" : "+l"(a) : "l"(x), "l"(y))
#define ADD2(a, x)    asm("add.rn.f32x2 %0, %0, %1;"     : "+l"(a) : "l"(x))

__device__ __forceinline__ u64 dupf(float w) {
    u64 u;
    const uint32_t b = __float_as_uint(w);
    asm("mov.b64 %0, {%1,%1};" : "=l"(u) : "r"(b));
    return u;
}

__global__ __launch_bounds__(THREADS, 6)
void raycast_kernel(const float* __restrict__ x,
                    const float* __restrict__ weight,
                    float* __restrict__ out,
                    int nplanes)
{
    __shared__ u64 tile[TILE];             // [19][55], 2 planes as f32x2
    __shared__ u64 bufV[NPOS];             // per-family partials
    __shared__ u64 bufH[NPOS];
    __shared__ u64 bufD1[NPOS];
    __shared__ u64 bufD2[NPOS];

    const int tid = threadIdx.x;
    const int g0  = blockIdx.x * PLANES;

    // ---- zero lateral pad columns (disjoint from data fill) ----
    for (int i = tid; i < BOARD * 36; i += THREADS) {
        const int y = i / 36;
        const int c = i - y * 36;
        const int col = (c < 18) ? c : (c + BOARD);   // [0,18) and [37,55)
        tile[y * PW + col] = 0ull;
    }

    // ---- data fill ----
    const bool full = (g0 + PLANES <= nplanes);
    for (int p = tid; p < NPOS; p += THREADS) {
        const int yy = p / BOARD;
        const int xx = p - yy * BOARD;
        float v0, v1;
        if (full) {
            v0 = x[g0 * NPOS + p];
            v1 = x[(g0 + 1) * NPOS + p];
        } else {
            v0 = (g0     < nplanes) ? x[g0 * NPOS + p]       : 0.f;
            v1 = (g0 + 1 < nplanes) ? x[(g0 + 1) * NPOS + p] : 0.f;
        }
        u64 v;
        asm("mov.b64 %0, {%1,%2};" : "=l"(v)
            : "r"(__float_as_uint(v0)), "r"(__float_as_uint(v1)));
        tile[yy * PW + xx + 18] = v;
    }

    // ---- per-thread line parameters (R11-verified mapping) ----
    const int lt = tid;
    int base, stride, fam, line;
    if (lt < 19)      { fam = 0; line = lt;      base = line + 18;      stride = PW;     }
    else if (lt < 38) { fam = 1; line = lt - 19; base = line * PW + 18; stride = 1;      }
    else if (lt < 75) { fam = 2; line = lt - 38; base = line;           stride = PW + 1; }
    else              { fam = 3; line = lt - 75; base = line + 18;      stride = PW - 1; }
    // fam2 (D1): cell k at (y=k, x=line-18+k) -> idx = k*PW + (line+k)
    // fam3 (D2): cell k at (y=k, x=line-k)    -> idx = k*PW + (line-k+18)

    // ---- weights straight from global (L2 broadcast), duplicated pairs ----
    const float* wsrc = weight + ((fam < 2) ? 0 : 18);
    u64 wr[18];
    #pragma unroll
    for (int i = 0; i < 18; i++) wr[i] = dupf(__ldg(wsrc + i));

    __syncthreads();

    // ---- preload line; transform: 342 FFMA2 on registers ----
    const u64* tp = tile;
    u64 ln[19];
    #pragma unroll
    for (int k = 0; k < BOARD; k++) ln[k] = tp[base + k * stride];

    u64 acc[19];
    #pragma unroll
    for (int j = 0; j < 19; j++) acc[j] = 0ull;

    #pragma unroll
    for (int k = 0; k < BOARD; k++) {
        const u64 v = ln[k];
        #pragma unroll
        for (int j = 0; j < BOARD; j++) {
            if (j == k) continue;
            const int d = (k > j) ? (k - j) : (j - k);
            FMA2(acc[j], v, wr[d - 1]);
        }
    }

    // ---- scatter line outputs (single family branch) ----
    if (fam == 0) {
        #pragma unroll
        for (int j = 0; j < BOARD; j++) bufV[j * BOARD + line] = acc[j];
    } else if (fam == 1) {
        #pragma unroll
        for (int j = 0; j < BOARD; j++) bufH[line * BOARD + j] = acc[j];
    } else if (fam == 2) {
        const int off = line - 18;            // x = j + off
        #pragma unroll
        for (int j = 0; j < BOARD; j++) {
            const int xx = j + off;
            if (xx >= 0 && xx < BOARD) bufD1[j * BOARD + xx] = acc[j];
        }
    } else {
        #pragma unroll
        for (int j = 0; j < BOARD; j++) {     // x = line - j
            const int xx = line - j;
            if (xx >= 0 && xx < BOARD) bufD2[j * BOARD + xx] = acc[j];
        }
    }

    __syncthreads();

    // ---- combine 4 partials, unpack, coalesced store per plane ----
    for (int p = tid; p < NPOS; p += THREADS) {
        u64 s = bufV[p];
        ADD2(s, bufH[p]);
        ADD2(s, bufD1[p]);
        ADD2(s, bufD2[p]);
        uint32_t p0, p1;
        asm("mov.b64 {%0,%1}, %2;" : "=r"(p0), "=r"(p1) : "l"(s));
        if (full) {
            out[g0 * NPOS + p]       = __uint_as_float(p0);
            out[(g0 + 1) * NPOS + p] = __uint_as_float(p1);
        } else {
            if (g0     < nplanes) out[g0 * NPOS + p]       = __uint_as_float(p0);
            if (g0 + 1 < nplanes) out[(g0 + 1) * NPOS + p] = __uint_as_float(p1);
        }
    }
}

extern "C" void kernel_launch(void* const* d_in, const int* in_sizes, int n_in,
                              void* d_out, int out_size)
{
    const float* x      = (const float*)d_in[0];   // [32,64,19,19]
    const float* weight = (const float*)d_in[1];   // [2,18]
    float* out          = (float*)d_out;

    const int nplanes = in_sizes[0] / NPOS;        // 2048
    const int grid = (nplanes + PLANES - 1) / PLANES;   // 1024

    raycast_kernel<<<grid, THREADS>>>(x, weight, out, nplanes);
}

// round 16
// speedup vs baseline: 2.0312x; 1.0997x over previous
#include <cuda_runtime.h>
#include <cuda_bf16.h>
#include <stdint.h>

// RayCastLayer R16: R15 champion (one 2-plane group per 112-thread CTA,
// full-line threads, register weights) with occupancy bound 6 -> 7 so the
// 1024-CTA grid fits in a single wave (148 * 7 = 1036 slots), plus unrolled
// fill/epilogue loops.

#define BOARD 19
#define NPOS  361
#define PW    55            // padded tile width (x shifted by +18)
#define TILE  (BOARD * PW)  // 1045 u64 entries
#define THREADS 112
#define PLANES 2

typedef unsigned long long u64;

#define FMA2(a, x, y) asm("fma.rn.f32x2 %0, %1, %2, %0;" : "+l"(a) : "l"(x), "l"(y))
#define ADD2(a, x)    asm("add.rn.f32x2 %0, %0, %1;"     : "+l"(a) : "l"(x))

__device__ __forceinline__ u64 dupf(float w) {
    u64 u;
    const uint32_t b = __float_as_uint(w);
    asm("mov.b64 %0, {%1,%1};" : "=l"(u) : "r"(b));
    return u;
}

__global__ __launch_bounds__(THREADS, 7)
void raycast_kernel(const float* __restrict__ x,
                    const float* __restrict__ weight,
                    float* __restrict__ out,
                    int nplanes)
{
    __shared__ u64 tile[TILE];             // [19][55], 2 planes as f32x2
    __shared__ u64 bufV[NPOS];             // per-family partials
    __shared__ u64 bufH[NPOS];
    __shared__ u64 bufD1[NPOS];
    __shared__ u64 bufD2[NPOS];

    const int tid = threadIdx.x;
    const int g0  = blockIdx.x * PLANES;

    // ---- zero lateral pad columns (disjoint from data fill) ----
    #pragma unroll
    for (int it = 0; it < 7; it++) {                  // 19*36=684 = 6.1*112
        const int i = tid + it * THREADS;
        if (i < BOARD * 36) {
            const int y = i / 36;
            const int c = i - y * 36;
            const int col = (c < 18) ? c : (c + BOARD);   // [0,18) and [37,55)
            tile[y * PW + col] = 0ull;
        }
    }

    // ---- data fill: 4 unrolled rounds over 361 positions ----
    const bool full = (g0 + PLANES <= nplanes);
    #pragma unroll
    for (int it = 0; it < 4; it++) {
        const int p = tid + it * THREADS;
        if (p < NPOS) {
            const int yy = p / BOARD;
            const int xx = p - yy * BOARD;
            float v0, v1;
            if (full) {
                v0 = x[g0 * NPOS + p];
                v1 = x[(g0 + 1) * NPOS + p];
            } else {
                v0 = (g0     < nplanes) ? x[g0 * NPOS + p]       : 0.f;
                v1 = (g0 + 1 < nplanes) ? x[(g0 + 1) * NPOS + p] : 0.f;
            }
            u64 v;
            asm("mov.b64 %0, {%1,%2};" : "=l"(v)
                : "r"(__float_as_uint(v0)), "r"(__float_as_uint(v1)));
            tile[yy * PW + xx + 18] = v;
        }
    }

    // ---- per-thread line parameters (R11-verified mapping) ----
    const int lt = tid;
    int base, stride, fam, line;
    if (lt < 19)      { fam = 0; line = lt;      base = line + 18;      stride = PW;     }
    else if (lt < 38) { fam = 1; line = lt - 19; base = line * PW + 18; stride = 1;      }
    else if (lt < 75) { fam = 2; line = lt - 38; base = line;           stride = PW + 1; }
    else              { fam = 3; line = lt - 75; base = line + 18;      stride = PW - 1; }
    // fam2 (D1): cell k at (y=k, x=line-18+k) -> idx = k*PW + (line+k)
    // fam3 (D2): cell k at (y=k, x=line-k)    -> idx = k*PW + (line-k+18)

    // ---- weights straight from global (L2 broadcast), duplicated pairs ----
    const float* wsrc = weight + ((fam < 2) ? 0 : 18);
    u64 wr[18];
    #pragma unroll
    for (int i = 0; i < 18; i++) wr[i] = dupf(__ldg(wsrc + i));

    __syncthreads();

    // ---- preload line; transform: 342 FFMA2 on registers ----
    const u64* tp = tile;
    u64 ln[19];
    #pragma unroll
    for (int k = 0; k < BOARD; k++) ln[k] = tp[base + k * stride];

    u64 acc[19];
    #pragma unroll
    for (int j = 0; j < 19; j++) acc[j] = 0ull;

    #pragma unroll
    for (int k = 0; k < BOARD; k++) {
        const u64 v = ln[k];
        #pragma unroll
        for (int j = 0; j < BOARD; j++) {
            if (j == k) continue;
            const int d = (k > j) ? (k - j) : (j - k);
            FMA2(acc[j], v, wr[d - 1]);
        }
    }

    // ---- scatter line outputs (single family branch) ----
    if (fam == 0) {
        #pragma unroll
        for (int j = 0; j < BOARD; j++) bufV[j * BOARD + line] = acc[j];
    } else if (fam == 1) {
        #pragma unroll
        for (int j = 0; j < BOARD; j++) bufH[line * BOARD + j] = acc[j];
    } else if (fam == 2) {
        const int off = line - 18;            // x = j + off
        #pragma unroll
        for (int j = 0; j < BOARD; j++) {
            const int xx = j + off;
            if (xx >= 0 && xx < BOARD) bufD1[j * BOARD + xx] = acc[j];
        }
    } else {
        #pragma unroll
        for (int j = 0; j < BOARD; j++) {     // x = line - j
            const int xx = line - j;
            if (xx >= 0 && xx < BOARD) bufD2[j * BOARD + xx] = acc[j];
        }
    }

    __syncthreads();

    // ---- combine 4 partials, unpack, coalesced store per plane ----
    #pragma unroll
    for (int it = 0; it < 4; it++) {
        const int p = tid + it * THREADS;
        if (p < NPOS) {
            u64 s = bufV[p];
            ADD2(s, bufH[p]);
            ADD2(s, bufD1[p]);
            ADD2(s, bufD2[p]);
            uint32_t p0, p1;
            asm("mov.b64 {%0,%1}, %2;" : "=r"(p0), "=r"(p1) : "l"(s));
            if (full) {
                out[g0 * NPOS + p]       = __uint_as_float(p0);
                out[(g0 + 1) * NPOS + p] = __uint_as_float(p1);
            } else {
                if (g0     < nplanes) out[g0 * NPOS + p]       = __uint_as_float(p0);
                if (g0 + 1 < nplanes) out[(g0 + 1) * NPOS + p] = __uint_as_float(p1);
            }
        }
    }
}

extern "C" void kernel_launch(void* const* d_in, const int* in_sizes, int n_in,
                              void* d_out, int out_size)
{
    const float* x      = (const float*)d_in[0];   // [32,64,19,19]
    const float* weight = (const float*)d_in[1];   // [2,18]
    float* out          = (float*)d_out;

    const int nplanes = in_sizes[0] / NPOS;        // 2048
    const int grid = (nplanes + PLANES - 1) / PLANES;   // 1024

    raycast_kernel<<<grid, THREADS>>>(x, weight, out, nplanes);
}